// round 10
// baseline (speedup 1.0000x reference)
#include <cuda_runtime.h>
#include <math.h>

// Problem dims (fixed by setup_inputs)
#define S   1024
#define B   64
#define IC  256
#define H   512
#define H2  1024
#define G4  2048
#define HB  (H*B)          // 32768
#define NBLK 128
#define LN_EPS 1e-5f

typedef unsigned long long u64;

// ---------------- device scratch (static: no allocation allowed) ----------------
__device__ float g_encT[(size_t)S*H*B];     // [t][h][b]   128 MB
__device__ float g_Px[(size_t)S*G4*B];      // [t][g][b]   512 MB
__device__ float g_Wxf[(size_t)G4*H];       // ln_w-folded x-weights, [g][k] 4 MB
__device__ float g_v[G4];                   // ln_w @ W^T
__device__ float g_cv[G4];                  // ln_b @ W^T + bias
__device__ float g_Sx[S*B];
__device__ float g_Qx[S*B];
__device__ float g_Sh[(S+1)*B];
__device__ float g_Qh[(S+1)*B];
__device__ float g_hl[2*HB];                // h * ln_w_h, [buf][h][b]
__device__ unsigned g_cnt;                  // grid barrier arrive counter
__device__ unsigned g_gen;                  // grid barrier generation

// ---------------- f32x2 packed math ----------------
__device__ __forceinline__ u64 pack2(float x, float y){
    u64 r; asm("mov.b64 %0, {%1,%2};" : "=l"(r) : "f"(x), "f"(y)); return r;
}
__device__ __forceinline__ float2 unpack2(u64 v){
    float2 f; asm("mov.b64 {%0,%1}, %2;" : "=f"(f.x), "=f"(f.y) : "l"(v)); return f;
}
__device__ __forceinline__ u64 ffma2(u64 a, u64 b, u64 c){
    u64 d; asm("fma.rn.f32x2 %0, %1, %2, %3;" : "=l"(d) : "l"(a), "l"(b), "l"(c)); return d;
}

__device__ __forceinline__ const float* wrow(const float* Wf, const float* Wi,
                                             const float* Wg, const float* Wo, int q){
    return q == 0 ? Wf : (q == 1 ? Wi : (q == 2 ? Wg : Wo));
}

// ---------------- init: reset all per-launch state (graph-replay safe) ----------------
__global__ void k_init(){
    int idx = blockIdx.x*blockDim.x + threadIdx.x;
    int stride = gridDim.x*blockDim.x;
    for (int i = idx; i < (S+1)*B; i += stride){ g_Sh[i] = 0.f; g_Qh[i] = 0.f; }
    for (int i = idx; i < 2*HB;    i += stride){ g_hl[i] = 0.f; }
    if (idx == 0){ g_cnt = 0u; g_gen = 0u; }
}

// ---------------- gate-row constants: v = lnw@W^T, cv = lnb@W^T + b ----------------
__global__ void k_vc(const float* __restrict__ lnw, const float* __restrict__ lnb,
                     const float* __restrict__ Wf, const float* __restrict__ Wi,
                     const float* __restrict__ Wg, const float* __restrict__ Wo,
                     const float* __restrict__ bf, const float* __restrict__ bi,
                     const float* __restrict__ bg, const float* __restrict__ bo){
    int g = blockIdx.x*blockDim.x + threadIdx.x;
    if (g >= G4) return;
    int q = g >> 9, r = g & 511;
    const float* W = wrow(Wf,Wi,Wg,Wo,q) + (size_t)r*H2;
    const float* bq = (q==0?bf:(q==1?bi:(q==2?bg:bo)));
    float v = 0.f, c = 0.f;
    for (int j = 0; j < H2; j++){ v += lnw[j]*W[j]; c += lnb[j]*W[j]; }
    g_v[g] = v;
    g_cv[g] = c + bq[r];
}

// ---------------- fold ln_w into x-part weights ----------------
__global__ void k_wxf(const float* __restrict__ lnw,
                      const float* __restrict__ Wf, const float* __restrict__ Wi,
                      const float* __restrict__ Wg, const float* __restrict__ Wo){
    int idx = blockIdx.x*blockDim.x + threadIdx.x;   // 2048 x 512
    int g = idx >> 9, k = idx & 511;
    int q = g >> 9, r = g & 511;
    const float* W = wrow(Wf,Wi,Wg,Wo,q);
    g_Wxf[idx] = W[(size_t)r*H2 + k] * lnw[k];
}

// ---------------- encoder conv as GEMM: encT[t][h][b] ----------------
__global__ void k_conv(const float* __restrict__ x, const float* __restrict__ cw){
    __shared__ float As[16][64];   // [kk][b]
    __shared__ float Bs[16][64];   // [kk][h]
    int t = blockIdx.x, h0 = blockIdx.y*64;
    int tid = threadIdx.x;
    int lb = tid >> 2, io = (tid & 3)*4;
    int ty = tid >> 4, tx = tid & 15;

    u64 acc[4][2];
    u64 z = pack2(0.f, 0.f);
#pragma unroll
    for (int i = 0; i < 4; i++){ acc[i][0] = z; acc[i][1] = z; }

    for (int c = 0; c < 48; c++){
        int ktap = c >> 4;
        int i0 = (c & 15)*16;
        int t2 = t + ktap - 1;
        float4 av;
        if ((unsigned)t2 < S)
            av = *(const float4*)(x + ((size_t)t2*B + lb)*IC + i0 + io);
        else
            av = make_float4(0.f,0.f,0.f,0.f);
        As[io+0][lb] = av.x; As[io+1][lb] = av.y;
        As[io+2][lb] = av.z; As[io+3][lb] = av.w;
        {
            const float* wp = cw + (size_t)(h0+lb)*768 + ktap;
            Bs[io+0][lb] = wp[(i0+io+0)*3];
            Bs[io+1][lb] = wp[(i0+io+1)*3];
            Bs[io+2][lb] = wp[(i0+io+2)*3];
            Bs[io+3][lb] = wp[(i0+io+3)*3];
        }
        __syncthreads();
#pragma unroll
        for (int kk = 0; kk < 16; kk++){
            const ulonglong2 ap = *(const ulonglong2*)&As[kk][tx*4];
            const float4 b4 = *(const float4*)&Bs[kk][ty*4];
            u64 w0 = pack2(b4.x, b4.x);
            u64 w1 = pack2(b4.y, b4.y);
            u64 w2 = pack2(b4.z, b4.z);
            u64 w3 = pack2(b4.w, b4.w);
            acc[0][0] = ffma2(w0, ap.x, acc[0][0]); acc[0][1] = ffma2(w0, ap.y, acc[0][1]);
            acc[1][0] = ffma2(w1, ap.x, acc[1][0]); acc[1][1] = ffma2(w1, ap.y, acc[1][1]);
            acc[2][0] = ffma2(w2, ap.x, acc[2][0]); acc[2][1] = ffma2(w2, ap.y, acc[2][1]);
            acc[3][0] = ffma2(w3, ap.x, acc[3][0]); acc[3][1] = ffma2(w3, ap.y, acc[3][1]);
        }
        __syncthreads();
    }
#pragma unroll
    for (int i = 0; i < 4; i++){
        int h = h0 + ty*4 + i;
        float2 lo = unpack2(acc[i][0]);
        float2 hi = unpack2(acc[i][1]);
        *(float4*)(g_encT + (size_t)t*HB + (size_t)h*64 + tx*4) =
            make_float4(lo.x, lo.y, hi.x, hi.y);
    }
}

// ---------------- per-(t,b) sums of encoder output ----------------
__global__ void k_sxqx(){
    int t = blockIdx.x;
    int tid = threadIdx.x;
    int b = tid & 63, hq = tid >> 6;
    float s = 0.f, q = 0.f;
    const float* base = g_encT + (size_t)t*HB + b;
    for (int h = hq; h < H; h += 4){
        float v = base[(size_t)h*64];
        s += v; q += v*v;
    }
    __shared__ float ss[4][64], qq[4][64];
    ss[hq][b] = s; qq[hq][b] = q;
    __syncthreads();
    if (tid < 64){
        g_Sx[t*B + tid] = ss[0][tid]+ss[1][tid]+ss[2][tid]+ss[3][tid];
        g_Qx[t*B + tid] = qq[0][tid]+qq[1][tid]+qq[2][tid]+qq[3][tid];
    }
}

// ---------------- Px GEMM: Px[t][g][b] = sum_h Wxf[g][h]*encT[t][h][b] ----------------
__global__ void k_px(){
    __shared__ float Ws[16][64];   // [kk][g]
    __shared__ float Es[16][64];   // [kk][b]
    int t = blockIdx.x, g0 = blockIdx.y*64;
    int tid = threadIdx.x;
    int lb = tid >> 2, io = (tid & 3)*4;
    int ekk = tid >> 4, eb = (tid & 15)*4;
    int ty = tid >> 4, tx = tid & 15;

    u64 acc[4][2];
    u64 z = pack2(0.f, 0.f);
#pragma unroll
    for (int i = 0; i < 4; i++){ acc[i][0] = z; acc[i][1] = z; }

    for (int c = 0; c < 32; c++){
        int k0 = c*16;
        float4 wv = *(const float4*)(g_Wxf + (size_t)(g0+lb)*H + k0 + io);
        Ws[io+0][lb] = wv.x; Ws[io+1][lb] = wv.y;
        Ws[io+2][lb] = wv.z; Ws[io+3][lb] = wv.w;
        *(float4*)&Es[ekk][eb] =
            *(const float4*)(g_encT + (size_t)t*HB + (size_t)(k0+ekk)*64 + eb);
        __syncthreads();
#pragma unroll
        for (int kk = 0; kk < 16; kk++){
            const ulonglong2 ap = *(const ulonglong2*)&Es[kk][tx*4];
            const float4 b4 = *(const float4*)&Ws[kk][ty*4];
            u64 w0 = pack2(b4.x, b4.x);
            u64 w1 = pack2(b4.y, b4.y);
            u64 w2 = pack2(b4.z, b4.z);
            u64 w3 = pack2(b4.w, b4.w);
            acc[0][0] = ffma2(w0, ap.x, acc[0][0]); acc[0][1] = ffma2(w0, ap.y, acc[0][1]);
            acc[1][0] = ffma2(w1, ap.x, acc[1][0]); acc[1][1] = ffma2(w1, ap.y, acc[1][1]);
            acc[2][0] = ffma2(w2, ap.x, acc[2][0]); acc[2][1] = ffma2(w2, ap.y, acc[2][1]);
            acc[3][0] = ffma2(w3, ap.x, acc[3][0]); acc[3][1] = ffma2(w3, ap.y, acc[3][1]);
        }
        __syncthreads();
    }
#pragma unroll
    for (int i = 0; i < 4; i++){
        int g = g0 + ty*4 + i;
        float2 lo = unpack2(acc[i][0]);
        float2 hi = unpack2(acc[i][1]);
        *(float4*)(g_Px + (size_t)t*G4*B + (size_t)g*64 + tx*4) =
            make_float4(lo.x, lo.y, hi.x, hi.y);
    }
}

// ---------------- grid barrier (all 128 blocks co-resident: 1 block/SM by smem) ------
__device__ __forceinline__ void gsync(){
    __syncthreads();
    if (threadIdx.x == 0){
        volatile unsigned* vg = &g_gen;
        unsigned old = *vg;
        __threadfence();
        if (atomicAdd(&g_cnt, 1u) == NBLK - 1u){
            g_cnt = 0u;
            __threadfence();
            atomicExch(&g_gen, old + 1u);
        } else {
            while (*vg == old) { }
        }
        __threadfence();
    }
    __syncthreads();
}

// ---------------- persistent LSTM recurrence: one kernel, 1024 steps ----------------
// Dynamic smem: WsmT2[512][16] u64 (w,w pairs, 64KB) | HLs[512][64] f32 (128KB) |
//               RED[256][8] u64 (16KB)  => 212992 B
__global__ void __launch_bounds__(256, 1)
k_persist(const float* __restrict__ Wf, const float* __restrict__ Wi,
          const float* __restrict__ Wg, const float* __restrict__ Wo,
          const float* __restrict__ lnw, float* __restrict__ out){
    extern __shared__ u64 dsm8[];
    u64*   WsmT2 = dsm8;                         // [k][gl] (w,w) pairs
    float* HLs   = (float*)(dsm8 + 8192);        // [k][b]
    u64*   RED   = (u64*)(HLs + 32768);          // [tid][8]

    __shared__ float mus[64], rss[64];
    __shared__ float gbuf[16][64];
    __shared__ float sred[4][64], qred[4][64];

    const int tid = threadIdx.x;
    const int hs  = blockIdx.x * 4;

    // ---- setup: load weight slice once, transposed + duplicated for f32x2 ----
    for (int it = tid; it < 8192; it += 256){
        int k  = it >> 4;
        int gl = it & 15;
        int q = gl >> 2, j = gl & 3;
        const float* W = wrow(Wf,Wi,Wg,Wo,q);
        float w = W[(size_t)(hs+j)*H2 + H + k];
        WsmT2[it] = pack2(w, w);
    }

    // dot-phase thread mapping
    const int ks = tid >> 6;            // 0..3  K split
    const int rq = (tid >> 4) & 3;      // 0..3  row quad (rows rq*4..+3)
    const int bg = tid & 15;            // 0..15 batch quad (b = bg*4..+3)

    // phase-A mapping (gate rows)
    const int agl = tid >> 4;           // 0..15
    const int ab4 = tid & 15;           // batch quad
    const int aq = agl >> 2, aj = agl & 3;
    const int ag = aq*512 + hs + aj;
    const float vg = g_v[ag];
    const float cg = g_cv[ag];

    // phase-B mapping (combine)
    const int bj = tid >> 6;            // 0..3 hidden unit
    const int bb = tid & 63;            // batch
    const int bh = hs + bj;
    const float lnwh = lnw[H + bh];
    float c_reg = 0.f;

    const u64 z2 = pack2(0.f, 0.f);

    for (int t = 0; t < S; t++){
        // ---- 1) stage hl[t] into smem (bypass L1: buffer written by other SMs) ----
        {
            const float4* src = (const float4*)(g_hl + (size_t)(t & 1)*HB);
            float4* dst = (float4*)HLs;
#pragma unroll 4
            for (int i = tid; i < 8192; i += 256)
                dst[i] = __ldcg(src + i);
        }
        // ---- 2) LN statistics per batch ----
        if (tid < 64){
            float sv = g_Sx[t*B + tid] + g_Sh[t*B + tid];
            float qv = g_Qx[t*B + tid] + g_Qh[t*B + tid];
            float mu = sv * (1.0f/1024.0f);
            float var = qv * (1.0f/1024.0f) - mu*mu;
            mus[tid] = mu;
            rss[tid] = rsqrtf(var + LN_EPS);
        }
        __syncthreads();

        // ---- 3) dot: 4 rows x 4 batches x K/4 per thread ----
        {
            u64 acc[4][2];
#pragma unroll
            for (int j = 0; j < 4; j++){ acc[j][0] = z2; acc[j][1] = z2; }
            const u64*   wb = WsmT2 + rq*4;
            const float* hb = HLs + bg*4;
#pragma unroll 8
            for (int kk = 0; kk < 128; kk++){
                int k = (kk << 2) | ks;
                const ulonglong2 w01 = *(const ulonglong2*)(wb + (size_t)k*16);
                const ulonglong2 w23 = *(const ulonglong2*)(wb + (size_t)k*16 + 2);
                const ulonglong2 hv  = *(const ulonglong2*)(hb + (size_t)k*64);
                acc[0][0] = ffma2(w01.x, hv.x, acc[0][0]); acc[0][1] = ffma2(w01.x, hv.y, acc[0][1]);
                acc[1][0] = ffma2(w01.y, hv.x, acc[1][0]); acc[1][1] = ffma2(w01.y, hv.y, acc[1][1]);
                acc[2][0] = ffma2(w23.x, hv.x, acc[2][0]); acc[2][1] = ffma2(w23.x, hv.y, acc[2][1]);
                acc[3][0] = ffma2(w23.y, hv.x, acc[3][0]); acc[3][1] = ffma2(w23.y, hv.y, acc[3][1]);
            }
            u64* rp = RED + (size_t)tid*8;
#pragma unroll
            for (int j = 0; j < 4; j++){ rp[j*2] = acc[j][0]; rp[j*2+1] = acc[j][1]; }
        }
        __syncthreads();

        // ---- 4) phase A: K-reduction + LN affine -> pre-activations ----
        {
            float2 s01 = make_float2(0.f,0.f), s23 = make_float2(0.f,0.f);
            int rq2 = agl >> 2, j2 = agl & 3;
#pragma unroll
            for (int kss = 0; kss < 4; kss++){
                const ulonglong2 p =
                    *(const ulonglong2*)(RED + (size_t)(kss*64 + rq2*16 + ab4)*8 + j2*2);
                float2 a = unpack2(p.x), b2 = unpack2(p.y);
                s01.x += a.x; s01.y += a.y; s23.x += b2.x; s23.y += b2.y;
            }
            int b0 = ab4*4;
            const float4 px = *(const float4*)(g_Px + (size_t)t*(G4*B) + (size_t)ag*64 + b0);
            float p0 = rss[b0+0]*(px.x + s01.x - mus[b0+0]*vg) + cg;
            float p1 = rss[b0+1]*(px.y + s01.y - mus[b0+1]*vg) + cg;
            float p2 = rss[b0+2]*(px.z + s23.x - mus[b0+2]*vg) + cg;
            float p3 = rss[b0+3]*(px.w + s23.y - mus[b0+3]*vg) + cg;
            *(float4*)&gbuf[agl][b0] = make_float4(p0, p1, p2, p3);
        }
        __syncthreads();

        // ---- 5) phase B: gate nonlinearities + cell/hidden update ----
        {
            float pf = gbuf[0*4 + bj][bb];
            float pi = gbuf[1*4 + bj][bb];
            float pg = gbuf[2*4 + bj][bb];
            float po = gbuf[3*4 + bj][bb];
            float f  = 1.f/(1.f + expf(-pf));
            float ii = 1.f/(1.f + expf(-pi));
            float gg = tanhf(pg);
            float o  = 1.f/(1.f + expf(-po));
            c_reg = f*c_reg + ii*gg;
            float hn = o * tanhf(c_reg);
            out[((size_t)t*B + bb)*H + bh] = hn;
            g_hl[(size_t)((t+1) & 1)*HB + (size_t)bh*64 + bb] = hn * lnwh;
            if (t == S-1){
                out[(size_t)S*B*H + (size_t)bb*H + bh] = hn;                 // hx
                out[(size_t)S*B*H + (size_t)B*H + (size_t)bb*H + bh] = c_reg; // cx
            }
            sred[bj][bb] = hn;
            qred[bj][bb] = hn*hn;
        }
        __syncthreads();

        // ---- 6) accumulate running hidden sums for next step's LN ----
        if (tid < 64){
            float s  = sred[0][tid]+sred[1][tid]+sred[2][tid]+sred[3][tid];
            float qv = qred[0][tid]+qred[1][tid]+qred[2][tid]+qred[3][tid];
            atomicAdd(&g_Sh[(t+1)*B + tid], s);
            atomicAdd(&g_Qh[(t+1)*B + tid], qv);
        }

        // ---- 7) grid barrier: all hl/Sh writes visible before next step ----
        gsync();
    }
}

// ---------------- launch ----------------
extern "C" void kernel_launch(void* const* d_in, const int* in_sizes, int n_in,
                              void* d_out, int out_size){
    const float* inputs = (const float*)d_in[0];
    const float* conv_w = (const float*)d_in[1];
    const float* ln_w   = (const float*)d_in[2];
    const float* ln_b   = (const float*)d_in[3];
    const float* Wf     = (const float*)d_in[4];
    const float* bf     = (const float*)d_in[5];
    const float* Wi     = (const float*)d_in[6];
    const float* bi     = (const float*)d_in[7];
    const float* Wg     = (const float*)d_in[8];
    const float* bg     = (const float*)d_in[9];
    const float* Wo     = (const float*)d_in[10];
    const float* bo     = (const float*)d_in[11];
    float* out = (float*)d_out;

    const int DYN = 8192*8 + 32768*4 + 2048*8;   // 212992 B
    cudaFuncSetAttribute(k_persist, cudaFuncAttributeMaxDynamicSharedMemorySize, DYN);

    k_init<<<256, 256>>>();
    k_vc<<<16, 128>>>(ln_w, ln_b, Wf, Wi, Wg, Wo, bf, bi, bg, bo);
    k_wxf<<<2048, 512>>>(ln_w, Wf, Wi, Wg, Wo);
    k_conv<<<dim3(S, H/64), 256>>>(inputs, conv_w);
    k_sxqx<<<S, 256>>>();
    k_px<<<dim3(S, G4/64), 256>>>();
    k_persist<<<NBLK, 256, DYN>>>(Wf, Wi, Wg, Wo, ln_w, out);
}

// round 15
// speedup vs baseline: 1.1052x; 1.1052x over previous
#include <cuda_runtime.h>
#include <math.h>

// Problem dims (fixed by setup_inputs)
#define S   1024
#define B   64
#define IC  256
#define H   512
#define H2  1024
#define G4  2048
#define HB  (H*B)          // 32768
#define NBLK 128
#define LN_EPS 1e-5f

typedef unsigned long long u64;

// ---------------- device scratch (static: no allocation allowed) ----------------
__device__ float g_encT[(size_t)S*H*B];     // [t][h][b]   128 MB
__device__ float g_Px[(size_t)S*G4*B];      // [t][g][b]   512 MB
__device__ float g_Wxf[(size_t)G4*H];       // ln_w-folded x-weights, [g][k] 4 MB
__device__ u64   g_WcT2[(size_t)768*H];     // conv weights, transposed + (w,w) dup, 3 MB
__device__ float g_v[G4];                   // ln_w @ W^T
__device__ float g_cv[G4];                  // ln_b @ W^T + bias
__device__ float g_Sx[S*B];
__device__ float g_Qx[S*B];
__device__ float g_hl[2*HB];                // raw h, [buf][h][b]
__device__ unsigned g_cnt;                  // grid barrier arrive counter
__device__ unsigned g_gen;                  // grid barrier generation

// ---------------- f32x2 packed math ----------------
__device__ __forceinline__ u64 pack2(float x, float y){
    u64 r; asm("mov.b64 %0, {%1,%2};" : "=l"(r) : "f"(x), "f"(y)); return r;
}
__device__ __forceinline__ float2 unpack2(u64 v){
    float2 f; asm("mov.b64 {%0,%1}, %2;" : "=f"(f.x), "=f"(f.y) : "l"(v)); return f;
}
__device__ __forceinline__ u64 ffma2(u64 a, u64 b, u64 c){
    u64 d; asm("fma.rn.f32x2 %0, %1, %2, %3;" : "=l"(d) : "l"(a), "l"(b), "l"(c)); return d;
}

__device__ __forceinline__ const float* wrow(const float* Wf, const float* Wi,
                                             const float* Wg, const float* Wo, int q){
    return q == 0 ? Wf : (q == 1 ? Wi : (q == 2 ? Wg : Wo));
}

// ---------------- init: reset all per-launch state (graph-replay safe) ----------------
__global__ void k_init(){
    int idx = blockIdx.x*blockDim.x + threadIdx.x;
    int stride = gridDim.x*blockDim.x;
    for (int i = idx; i < 2*HB; i += stride){ g_hl[i] = 0.f; }
    if (idx == 0){ g_cnt = 0u; g_gen = 0u; }
}

// ---------------- gate-row constants: v = lnw@W^T, cv = lnb@W^T + b ----------------
__global__ void k_vc(const float* __restrict__ lnw, const float* __restrict__ lnb,
                     const float* __restrict__ Wf, const float* __restrict__ Wi,
                     const float* __restrict__ Wg, const float* __restrict__ Wo,
                     const float* __restrict__ bf, const float* __restrict__ bi,
                     const float* __restrict__ bg, const float* __restrict__ bo){
    int g = blockIdx.x*blockDim.x + threadIdx.x;
    if (g >= G4) return;
    int q = g >> 9, r = g & 511;
    const float* W = wrow(Wf,Wi,Wg,Wo,q) + (size_t)r*H2;
    const float* bq = (q==0?bf:(q==1?bi:(q==2?bg:bo)));
    float v = 0.f, c = 0.f;
    for (int j = 0; j < H2; j++){ v += lnw[j]*W[j]; c += lnb[j]*W[j]; }
    g_v[g] = v;
    g_cv[g] = c + bq[r];
}

// ---------------- fold ln_w into x-part weights ----------------
__global__ void k_wxf(const float* __restrict__ lnw,
                      const float* __restrict__ Wf, const float* __restrict__ Wi,
                      const float* __restrict__ Wg, const float* __restrict__ Wo){
    int idx = blockIdx.x*blockDim.x + threadIdx.x;   // 2048 x 512
    int g = idx >> 9, k = idx & 511;
    int q = g >> 9, r = g & 511;
    const float* W = wrow(Wf,Wi,Wg,Wo,q);
    g_Wxf[idx] = W[(size_t)r*H2 + k] * lnw[k];
}

// ---------------- transpose + duplicate conv weights: g_WcT2[ktap*256+i][h] ----------------
__global__ void k_wct(const float* __restrict__ cw){
    int idx = blockIdx.x*blockDim.x + threadIdx.x;   // 768 x 512
    int kidx = idx >> 9, h = idx & 511;
    int i = kidx & 255, ktap = kidx >> 8;
    float w = cw[(size_t)h*768 + i*3 + ktap];
    g_WcT2[idx] = pack2(w, w);
}

// ---------------- encoder conv as GEMM: encT[t][h][b], 128h x 64b tile, 8x8 micro ----
__global__ void __launch_bounds__(128)
k_conv(const float* __restrict__ x){
    __shared__ u64   Ws2[16][130];   // (w,w) dup per [kk][h_local]
    __shared__ float Es[16][64];     // inputs [kk][b]
    const int t = blockIdx.x, h0 = blockIdx.y*128;
    const int tid = threadIdx.x;
    const int ty = tid >> 3, tx = tid & 7;

    u64 acc[8][4];
    const u64 z = pack2(0.f, 0.f);
#pragma unroll
    for (int r = 0; r < 8; r++){ acc[r][0]=z; acc[r][1]=z; acc[r][2]=z; acc[r][3]=z; }

    for (int c = 0; c < 48; c++){
        const int ktap = c >> 4;
        const int i0   = (c & 15)*16;
        const int t2   = t + ktap - 1;
        // weights: 2048 u64 per chunk, already duplicated in g_WcT2
#pragma unroll
        for (int j = 0; j < 8; j++){
            int e  = (tid + 128*j)*2;
            int kk = e >> 7, h = e & 127;
            ulonglong2 v = *(const ulonglong2*)(g_WcT2 +
                           (size_t)(ktap*256 + i0 + kk)*512 + h0 + h);
            *(ulonglong2*)&Ws2[kk][h] = v;
        }
        // inputs tile: Es[i_local][b]
#pragma unroll
        for (int j = 0; j < 2; j++){
            int idx = tid*2 + j;
            int b = idx >> 2, m = idx & 3;
            float4 v;
            if ((unsigned)t2 < S)
                v = *(const float4*)(x + ((size_t)t2*B + b)*IC + i0 + m*4);
            else
                v = make_float4(0.f,0.f,0.f,0.f);
            Es[m*4+0][b] = v.x; Es[m*4+1][b] = v.y;
            Es[m*4+2][b] = v.z; Es[m*4+3][b] = v.w;
        }
        __syncthreads();
#pragma unroll
        for (int kk = 0; kk < 16; kk++){
            const ulonglong2 w01 = *(const ulonglong2*)&Ws2[kk][ty*8];
            const ulonglong2 w23 = *(const ulonglong2*)&Ws2[kk][ty*8+2];
            const ulonglong2 w45 = *(const ulonglong2*)&Ws2[kk][ty*8+4];
            const ulonglong2 w67 = *(const ulonglong2*)&Ws2[kk][ty*8+6];
            const ulonglong2 ha  = *(const ulonglong2*)&Es[kk][tx*8];
            const ulonglong2 hb  = *(const ulonglong2*)&Es[kk][tx*8+4];
            acc[0][0]=ffma2(w01.x,ha.x,acc[0][0]); acc[0][1]=ffma2(w01.x,ha.y,acc[0][1]);
            acc[0][2]=ffma2(w01.x,hb.x,acc[0][2]); acc[0][3]=ffma2(w01.x,hb.y,acc[0][3]);
            acc[1][0]=ffma2(w01.y,ha.x,acc[1][0]); acc[1][1]=ffma2(w01.y,ha.y,acc[1][1]);
            acc[1][2]=ffma2(w01.y,hb.x,acc[1][2]); acc[1][3]=ffma2(w01.y,hb.y,acc[1][3]);
            acc[2][0]=ffma2(w23.x,ha.x,acc[2][0]); acc[2][1]=ffma2(w23.x,ha.y,acc[2][1]);
            acc[2][2]=ffma2(w23.x,hb.x,acc[2][2]); acc[2][3]=ffma2(w23.x,hb.y,acc[2][3]);
            acc[3][0]=ffma2(w23.y,ha.x,acc[3][0]); acc[3][1]=ffma2(w23.y,ha.y,acc[3][1]);
            acc[3][2]=ffma2(w23.y,hb.x,acc[3][2]); acc[3][3]=ffma2(w23.y,hb.y,acc[3][3]);
            acc[4][0]=ffma2(w45.x,ha.x,acc[4][0]); acc[4][1]=ffma2(w45.x,ha.y,acc[4][1]);
            acc[4][2]=ffma2(w45.x,hb.x,acc[4][2]); acc[4][3]=ffma2(w45.x,hb.y,acc[4][3]);
            acc[5][0]=ffma2(w45.y,ha.x,acc[5][0]); acc[5][1]=ffma2(w45.y,ha.y,acc[5][1]);
            acc[5][2]=ffma2(w45.y,hb.x,acc[5][2]); acc[5][3]=ffma2(w45.y,hb.y,acc[5][3]);
            acc[6][0]=ffma2(w67.x,ha.x,acc[6][0]); acc[6][1]=ffma2(w67.x,ha.y,acc[6][1]);
            acc[6][2]=ffma2(w67.x,hb.x,acc[6][2]); acc[6][3]=ffma2(w67.x,hb.y,acc[6][3]);
            acc[7][0]=ffma2(w67.y,ha.x,acc[7][0]); acc[7][1]=ffma2(w67.y,ha.y,acc[7][1]);
            acc[7][2]=ffma2(w67.y,hb.x,acc[7][2]); acc[7][3]=ffma2(w67.y,hb.y,acc[7][3]);
        }
        __syncthreads();
    }
#pragma unroll
    for (int r = 0; r < 8; r++){
        int h = h0 + ty*8 + r;
        float2 a = unpack2(acc[r][0]), b2 = unpack2(acc[r][1]);
        float2 c2 = unpack2(acc[r][2]), d2 = unpack2(acc[r][3]);
        float* o = g_encT + (size_t)t*HB + (size_t)h*64 + tx*8;
        *(float4*)o       = make_float4(a.x, a.y, b2.x, b2.y);
        *(float4*)(o + 4) = make_float4(c2.x, c2.y, d2.x, d2.y);
    }
}

// ---------------- per-(t,b) sums of encoder output ----------------
__global__ void k_sxqx(){
    int t = blockIdx.x;
    int tid = threadIdx.x;
    int b = tid & 63, hq = tid >> 6;
    float s = 0.f, q = 0.f;
    const float* base = g_encT + (size_t)t*HB + b;
    for (int h = hq; h < H; h += 4){
        float v = base[(size_t)h*64];
        s += v; q += v*v;
    }
    __shared__ float ss[4][64], qq[4][64];
    ss[hq][b] = s; qq[hq][b] = q;
    __syncthreads();
    if (tid < 64){
        g_Sx[t*B + tid] = ss[0][tid]+ss[1][tid]+ss[2][tid]+ss[3][tid];
        g_Qx[t*B + tid] = qq[0][tid]+qq[1][tid]+qq[2][tid]+qq[3][tid];
    }
}

// ---------------- Px GEMM: Px[t][g][b] = sum_k Wxf[g][k]*encT[t][k][b] ----------------
// 128g x 64b tile, 8x8 micro, K=512
__global__ void __launch_bounds__(128)
k_px(){
    __shared__ u64   Ws2[16][130];
    __shared__ float Es[16][64];
    const int t = blockIdx.x, g0 = blockIdx.y*128;
    const int tid = threadIdx.x;
    const int ty = tid >> 3, tx = tid & 7;

    u64 acc[8][4];
    const u64 z = pack2(0.f, 0.f);
#pragma unroll
    for (int r = 0; r < 8; r++){ acc[r][0]=z; acc[r][1]=z; acc[r][2]=z; acc[r][3]=z; }

    for (int c = 0; c < 32; c++){
        const int k0 = c*16;
        // weights: thread owns one g row, duplicates on store
#pragma unroll
        for (int m = 0; m < 4; m++){
            float4 wv = *(const float4*)(g_Wxf + (size_t)(g0+tid)*H + k0 + m*4);
            Ws2[m*4+0][tid] = pack2(wv.x, wv.x);
            Ws2[m*4+1][tid] = pack2(wv.y, wv.y);
            Ws2[m*4+2][tid] = pack2(wv.z, wv.z);
            Ws2[m*4+3][tid] = pack2(wv.w, wv.w);
        }
#pragma unroll
        for (int j = 0; j < 2; j++){
            int idx = tid*2 + j;
            int kk = idx >> 4, b4 = (idx & 15)*4;
            *(float4*)&Es[kk][b4] =
                *(const float4*)(g_encT + (size_t)t*HB + (size_t)(k0+kk)*64 + b4);
        }
        __syncthreads();
#pragma unroll
        for (int kk = 0; kk < 16; kk++){
            const ulonglong2 w01 = *(const ulonglong2*)&Ws2[kk][ty*8];
            const ulonglong2 w23 = *(const ulonglong2*)&Ws2[kk][ty*8+2];
            const ulonglong2 w45 = *(const ulonglong2*)&Ws2[kk][ty*8+4];
            const ulonglong2 w67 = *(const ulonglong2*)&Ws2[kk][ty*8+6];
            const ulonglong2 ha  = *(const ulonglong2*)&Es[kk][tx*8];
            const ulonglong2 hb  = *(const ulonglong2*)&Es[kk][tx*8+4];
            acc[0][0]=ffma2(w01.x,ha.x,acc[0][0]); acc[0][1]=ffma2(w01.x,ha.y,acc[0][1]);
            acc[0][2]=ffma2(w01.x,hb.x,acc[0][2]); acc[0][3]=ffma2(w01.x,hb.y,acc[0][3]);
            acc[1][0]=ffma2(w01.y,ha.x,acc[1][0]); acc[1][1]=ffma2(w01.y,ha.y,acc[1][1]);
            acc[1][2]=ffma2(w01.y,hb.x,acc[1][2]); acc[1][3]=ffma2(w01.y,hb.y,acc[1][3]);
            acc[2][0]=ffma2(w23.x,ha.x,acc[2][0]); acc[2][1]=ffma2(w23.x,ha.y,acc[2][1]);
            acc[2][2]=ffma2(w23.x,hb.x,acc[2][2]); acc[2][3]=ffma2(w23.x,hb.y,acc[2][3]);
            acc[3][0]=ffma2(w23.y,ha.x,acc[3][0]); acc[3][1]=ffma2(w23.y,ha.y,acc[3][1]);
            acc[3][2]=ffma2(w23.y,hb.x,acc[3][2]); acc[3][3]=ffma2(w23.y,hb.y,acc[3][3]);
            acc[4][0]=ffma2(w45.x,ha.x,acc[4][0]); acc[4][1]=ffma2(w45.x,ha.y,acc[4][1]);
            acc[4][2]=ffma2(w45.x,hb.x,acc[4][2]); acc[4][3]=ffma2(w45.x,hb.y,acc[4][3]);
            acc[5][0]=ffma2(w45.y,ha.x,acc[5][0]); acc[5][1]=ffma2(w45.y,ha.y,acc[5][1]);
            acc[5][2]=ffma2(w45.y,hb.x,acc[5][2]); acc[5][3]=ffma2(w45.y,hb.y,acc[5][3]);
            acc[6][0]=ffma2(w67.x,ha.x,acc[6][0]); acc[6][1]=ffma2(w67.x,ha.y,acc[6][1]);
            acc[6][2]=ffma2(w67.x,hb.x,acc[6][2]); acc[6][3]=ffma2(w67.x,hb.y,acc[6][3]);
            acc[7][0]=ffma2(w67.y,ha.x,acc[7][0]); acc[7][1]=ffma2(w67.y,ha.y,acc[7][1]);
            acc[7][2]=ffma2(w67.y,hb.x,acc[7][2]); acc[7][3]=ffma2(w67.y,hb.y,acc[7][3]);
        }
        __syncthreads();
    }
#pragma unroll
    for (int r = 0; r < 8; r++){
        int g = g0 + ty*8 + r;
        float2 a = unpack2(acc[r][0]), b2 = unpack2(acc[r][1]);
        float2 c2 = unpack2(acc[r][2]), d2 = unpack2(acc[r][3]);
        float* o = g_Px + (size_t)t*(G4*B) + (size_t)g*64 + tx*8;
        *(float4*)o       = make_float4(a.x, a.y, b2.x, b2.y);
        *(float4*)(o + 4) = make_float4(c2.x, c2.y, d2.x, d2.y);
    }
}

// ---------------- grid barrier (128 blocks, 1/SM by smem -> co-resident) ----------------
__device__ __forceinline__ void gsync(){
    __syncthreads();
    if (threadIdx.x == 0){
        volatile unsigned* vg = &g_gen;
        unsigned old = *vg;
        __threadfence();
        if (atomicAdd(&g_cnt, 1u) == NBLK - 1u){
            g_cnt = 0u;
            __threadfence();
            atomicExch(&g_gen, old + 1u);
        } else {
            while (*vg == old) { }
        }
        __threadfence();
    }
    __syncthreads();
}

// ---------------- persistent LSTM recurrence: one kernel, 1024 steps ----------------
// Dynamic smem: WsmT2[512][16] u64 (lnw-folded, dup, 64KB) | HLs[512][64] f32 (128KB) |
//               RED[256][8] u64 (16KB)  => 212992 B
__global__ void __launch_bounds__(256, 1)
k_persist(const float* __restrict__ Wf, const float* __restrict__ Wi,
          const float* __restrict__ Wg, const float* __restrict__ Wo,
          const float* __restrict__ lnw, float* __restrict__ out){
    extern __shared__ u64 dsm8[];
    u64*   WsmT2 = dsm8;                         // [k][gl] (w*lnw, w*lnw) pairs
    float* HLs   = (float*)(dsm8 + 8192);        // [k][b] raw h
    u64*   RED   = (u64*)(HLs + 32768);          // [tid][8]

    __shared__ float mus[64], rss[64];
    __shared__ float gbuf[16][64];
    __shared__ float sredA[16][64], qredA[16][64];

    const int tid = threadIdx.x;
    const int hs  = blockIdx.x * 4;

    // ---- setup: weight slice, transposed + lnw-folded + duplicated ----
    for (int it = tid; it < 8192; it += 256){
        int k  = it >> 4;
        int gl = it & 15;
        int q = gl >> 2, j = gl & 3;
        const float* W = wrow(Wf,Wi,Wg,Wo,q);
        float w = W[(size_t)(hs+j)*H2 + H + k] * lnw[H + k];
        WsmT2[it] = pack2(w, w);
    }

    // dot-phase mapping
    const int ks = tid >> 6;            // 0..3  K split
    const int rq = (tid >> 4) & 3;      // 0..3  row quad
    const int bg = tid & 15;            // 0..15 batch quad

    // phase-A mapping (gate rows)
    const int agl = tid >> 4;           // 0..15
    const int ab4 = tid & 15;
    const int aq = agl >> 2, aj = agl & 3;
    const int ag = aq*512 + hs + aj;
    const float vg = g_v[ag];
    const float cg = g_cv[ag];

    // phase-B mapping (combine)
    const int bj = tid >> 6;
    const int bb = tid & 63;
    const int bh = hs + bj;
    float c_reg = 0.f;

    const u64 z2 = pack2(0.f, 0.f);

    for (int t = 0; t < S; t++){
        // ---- prefetch this step's Px slice + x-part LN sums (hidden under dot) ----
        const float4 px = *(const float4*)(g_Px + (size_t)t*(G4*B) + (size_t)ag*64 + ab4*4);
        float sx = 0.f, qx = 0.f;
        if (tid < 64){ sx = g_Sx[t*B + tid]; qx = g_Qx[t*B + tid]; }

        // ---- pipelined staging (4 chunks) + dot ----
        const float4* src = (const float4*)(g_hl + (size_t)(t & 1)*HB);
        float4 R[8];
#pragma unroll
        for (int j = 0; j < 8; j++) R[j] = __ldcg(src + tid + 256*j);

        float4 s4 = make_float4(0.f,0.f,0.f,0.f);
        float4 q4 = make_float4(0.f,0.f,0.f,0.f);
        u64 acc[4][2];
#pragma unroll
        for (int j = 0; j < 4; j++){ acc[j][0] = z2; acc[j][1] = z2; }

#pragma unroll
        for (int c = 0; c < 4; c++){
            float4* dst = (float4*)HLs + c*2048;
#pragma unroll
            for (int j = 0; j < 8; j++){
                float4 v = R[j];
                dst[tid + 256*j] = v;
                s4.x += v.x; s4.y += v.y; s4.z += v.z; s4.w += v.w;
                q4.x += v.x*v.x; q4.y += v.y*v.y; q4.z += v.z*v.z; q4.w += v.w*v.w;
            }
            if (c < 3){
#pragma unroll
                for (int j = 0; j < 8; j++)
                    R[j] = __ldcg(src + (c+1)*2048 + tid + 256*j);
            } else {
                *(float4*)&sredA[tid>>4][(tid&15)*4] = s4;
                *(float4*)&qredA[tid>>4][(tid&15)*4] = q4;
            }
            __syncthreads();
            // dot over chunk c: kk in [c*32, c*32+32), k = (kk<<2)|ks
            const u64*   wb = WsmT2 + rq*4 + (size_t)((c*128) | ks)*16;
            const float* hb = HLs    + bg*4 + (size_t)((c*128) | ks)*64;
#pragma unroll 8
            for (int kk = 0; kk < 32; kk++){
                const ulonglong2 w01 = *(const ulonglong2*)(wb + (size_t)kk*64);
                const ulonglong2 w23 = *(const ulonglong2*)(wb + (size_t)kk*64 + 2);
                const ulonglong2 hv  = *(const ulonglong2*)(hb + (size_t)kk*256);
                acc[0][0] = ffma2(w01.x, hv.x, acc[0][0]); acc[0][1] = ffma2(w01.x, hv.y, acc[0][1]);
                acc[1][0] = ffma2(w01.y, hv.x, acc[1][0]); acc[1][1] = ffma2(w01.y, hv.y, acc[1][1]);
                acc[2][0] = ffma2(w23.x, hv.x, acc[2][0]); acc[2][1] = ffma2(w23.x, hv.y, acc[2][1]);
                acc[3][0] = ffma2(w23.y, hv.x, acc[3][0]); acc[3][1] = ffma2(w23.y, hv.y, acc[3][1]);
            }
        }

        // ---- LN statistics (sredA valid: written before last chunk's sync) ----
        if (tid < 64){
            float s = 0.f, q = 0.f;
#pragma unroll
            for (int r = 0; r < 16; r++){ s += sredA[r][tid]; q += qredA[r][tid]; }
            float mu = (sx + s) * (1.0f/1024.0f);
            float var = (qx + q) * (1.0f/1024.0f) - mu*mu;
            mus[tid] = mu;
            rss[tid] = rsqrtf(var + LN_EPS);
        }

        // ---- K-split partials to smem ----
        {
            u64* rp = RED + (size_t)tid*8;
#pragma unroll
            for (int j = 0; j < 4; j++){
                rp[j*2]   = acc[j][0];
                rp[j*2+1] = acc[j][1];
                acc[j][0] = z2; acc[j][1] = z2;
            }
        }
        __syncthreads();

        // ---- phase A: K-reduction + LN affine -> pre-activations ----
        {
            float2 s01 = make_float2(0.f,0.f), s23 = make_float2(0.f,0.f);
            int rq2 = agl >> 2, j2 = agl & 3;
#pragma unroll
            for (int kss = 0; kss < 4; kss++){
                const ulonglong2 p =
                    *(const ulonglong2*)(RED + (size_t)(kss*64 + rq2*16 + ab4)*8 + j2*2);
                float2 a = unpack2(p.x), b2 = unpack2(p.y);
                s01.x += a.x; s01.y += a.y; s23.x += b2.x; s23.y += b2.y;
            }
            int b0 = ab4*4;
            float p0 = rss[b0+0]*(px.x + s01.x - mus[b0+0]*vg) + cg;
            float p1 = rss[b0+1]*(px.y + s01.y - mus[b0+1]*vg) + cg;
            float p2 = rss[b0+2]*(px.z + s23.x - mus[b0+2]*vg) + cg;
            float p3 = rss[b0+3]*(px.w + s23.y - mus[b0+3]*vg) + cg;
            *(float4*)&gbuf[agl][b0] = make_float4(p0, p1, p2, p3);
        }
        __syncthreads();

        // ---- phase B: gate nonlinearities + cell/hidden update ----
        {
            float pf = gbuf[0*4 + bj][bb];
            float pi = gbuf[1*4 + bj][bb];
            float pg = gbuf[2*4 + bj][bb];
            float po = gbuf[3*4 + bj][bb];
            float f  = 1.f/(1.f + expf(-pf));
            float ii = 1.f/(1.f + expf(-pi));
            float gg = tanhf(pg);
            float o  = 1.f/(1.f + expf(-po));
            c_reg = f*c_reg + ii*gg;
            float hn = o * tanhf(c_reg);
            out[((size_t)t*B + bb)*H + bh] = hn;
            g_hl[(size_t)((t+1) & 1)*HB + (size_t)bh*64 + bb] = hn;
            if (t == S-1){
                out[(size_t)S*B*H + (size_t)bb*H + bh] = hn;                  // hx
                out[(size_t)S*B*H + (size_t)B*H + (size_t)bb*H + bh] = c_reg; // cx
            }
        }

        // ---- grid barrier: h writes visible before next step's staging ----
        gsync();
    }
}

// ---------------- launch ----------------
extern "C" void kernel_launch(void* const* d_in, const int* in_sizes, int n_in,
                              void* d_out, int out_size){
    const float* inputs = (const float*)d_in[0];
    const float* conv_w = (const float*)d_in[1];
    const float* ln_w   = (const float*)d_in[2];
    const float* ln_b   = (const float*)d_in[3];
    const float* Wf     = (const float*)d_in[4];
    const float* bf     = (const float*)d_in[5];
    const float* Wi     = (const float*)d_in[6];
    const float* bi     = (const float*)d_in[7];
    const float* Wg     = (const float*)d_in[8];
    const float* bg     = (const float*)d_in[9];
    const float* Wo     = (const float*)d_in[10];
    const float* bo     = (const float*)d_in[11];
    float* out = (float*)d_out;

    const int DYN = 8192*8 + 32768*4 + 2048*8;   // 212992 B
    cudaFuncSetAttribute(k_persist, cudaFuncAttributeMaxDynamicSharedMemorySize, DYN);

    k_init<<<256, 256>>>();
    k_vc<<<16, 128>>>(ln_w, ln_b, Wf, Wi, Wg, Wo, bf, bi, bg, bo);
    k_wxf<<<2048, 512>>>(ln_w, Wf, Wi, Wg, Wo);
    k_wct<<<768, 512>>>(conv_w);
    k_conv<<<dim3(S, 4), 128>>>(inputs);
    k_sxqx<<<S, 256>>>();
    k_px<<<dim3(S, 16), 128>>>();
    k_persist<<<NBLK, 256, DYN>>>(Wf, Wi, Wg, Wo, ln_w, out);
}